// round 2
// baseline (speedup 1.0000x reference)
#include <cuda_runtime.h>
#include <cuda_bf16.h>
#include <math.h>

#define BOX_P 32
#define PATCH_ELEMS (BOX_P * BOX_P)   // 1024
#define THREADS 256
#define EPSF 1e-6f

__global__ void lp_zero_out(float* out) {
    if (threadIdx.x == 0) out[0] = 0.0f;
}

__global__ __launch_bounds__(THREADS)
void lp_pearson_kernel(const float* __restrict__ pred,
                       const float* __restrict__ gt,
                       const int*   __restrict__ x0,
                       const int*   __restrict__ y0,
                       float* __restrict__ out,
                       int n_corr, int W)
{
    const int b = blockIdx.x;
    const int X = x0[b];
    const int Y = y0[b];
    const float* __restrict__ pbase = pred + (size_t)X * W + Y;
    const float* __restrict__ gbase = gt   + (size_t)X * W + Y;

    const int t = threadIdx.x;

    float sp = 0.f, sg = 0.f, spp = 0.f, sgg = 0.f, spg = 0.f;

    // 1024 elements / 256 threads = 4 per thread.
    // idx -> (row i = idx>>5, col j = idx&31); lanes in a warp cover one row
    // segment of 32 contiguous floats -> coalesced 128B (+misalign sector).
    #pragma unroll
    for (int k = 0; k < PATCH_ELEMS / THREADS; k++) {
        const int idx = t + k * THREADS;
        const int i = idx >> 5;
        const int j = idx & 31;
        const size_t off = (size_t)i * W + j;
        const float p = __ldg(pbase + off);
        const float g = __ldg(gbase + off);
        sp  += p;
        sg  += g;
        spp += p * p;
        sgg += g * g;
        spg += p * g;
    }

    // Warp reduction of the 5 sums
    #pragma unroll
    for (int off = 16; off > 0; off >>= 1) {
        sp  += __shfl_down_sync(0xFFFFFFFFu, sp,  off);
        sg  += __shfl_down_sync(0xFFFFFFFFu, sg,  off);
        spp += __shfl_down_sync(0xFFFFFFFFu, spp, off);
        sgg += __shfl_down_sync(0xFFFFFFFFu, sgg, off);
        spg += __shfl_down_sync(0xFFFFFFFFu, spg, off);
    }

    __shared__ float sh[5][THREADS / 32];
    const int lane = t & 31;
    const int w    = t >> 5;
    if (lane == 0) {
        sh[0][w] = sp;  sh[1][w] = sg;  sh[2][w] = spp;
        sh[3][w] = sgg; sh[4][w] = spg;
    }
    __syncthreads();

    if (t == 0) {
        float Sp = 0.f, Sg = 0.f, Spp = 0.f, Sgg = 0.f, Spg = 0.f;
        #pragma unroll
        for (int i = 0; i < THREADS / 32; i++) {
            Sp  += sh[0][i];
            Sg  += sh[1][i];
            Spp += sh[2][i];
            Sgg += sh[3][i];
            Spg += sh[4][i];
        }
        const float P    = (float)PATCH_ELEMS;
        const float invP = 1.0f / P;
        const float mp = Sp * invP;
        const float mg = Sg * invP;
        // unbiased (ddof=1) variance, matching torch.std / jnp.std(ddof=1)
        const float varp = (Spp - Sp * mp) / (P - 1.0f);
        const float varg = (Sgg - Sg * mg) / (P - 1.0f);
        const float sdp = sqrtf(fmaxf(varp, 0.f)) + EPSF;
        const float sdg = sqrtf(fmaxf(varg, 0.f)) + EPSF;
        const float cov = Spg - Sp * mg;   // = Spg - Sp*Sg/P
        const float co  = cov / (P * sdp * sdg);
        atomicAdd(out, (1.0f - co) / (float)n_corr);
    }
}

extern "C" void kernel_launch(void* const* d_in, const int* in_sizes, int n_in,
                              void* d_out, int out_size)
{
    const float* pred = (const float*)d_in[0];
    const float* gt   = (const float*)d_in[1];
    const int*   x0   = (const int*)d_in[2];
    const int*   y0   = (const int*)d_in[3];
    float* out = (float*)d_out;

    const int n_corr = in_sizes[2];

    // Derive W from the (square, C=1) image element count instead of hardcoding.
    int W = 1;
    while ((long long)W * W < (long long)in_sizes[0]) W <<= 1;

    lp_zero_out<<<1, 32>>>(out);
    lp_pearson_kernel<<<n_corr, THREADS>>>(pred, gt, x0, y0, out, n_corr, W);
}

// round 3
// speedup vs baseline: 1.0817x; 1.0817x over previous
#include <cuda_runtime.h>
#include <cuda_bf16.h>
#include <math.h>

#define BOX_P 32
#define PATCH_ELEMS (BOX_P * BOX_P)   // 1024
#define WARPS_PER_CTA 8
#define THREADS (WARPS_PER_CTA * 32)
#define EPSF 1e-6f

__global__ void lp_zero_out(float* out) {
    if (threadIdx.x == 0) out[0] = 0.0f;
}

__global__ __launch_bounds__(THREADS)
void lp_pearson_warp_kernel(const float* __restrict__ pred,
                            const float* __restrict__ gt,
                            const int*   __restrict__ x0,
                            const int*   __restrict__ y0,
                            float* __restrict__ out,
                            int n_corr, int W)
{
    const int warp = threadIdx.x >> 5;
    const int lane = threadIdx.x & 31;
    const int b = blockIdx.x * WARPS_PER_CTA + warp;
    if (b >= n_corr) return;

    const int X = x0[b];
    const int Y = y0[b];
    // lane owns column `lane`; walk 32 rows -> 64 loads deep per lane.
    const float* __restrict__ pbase = pred + (size_t)X * W + Y + lane;
    const float* __restrict__ gbase = gt   + (size_t)X * W + Y + lane;

    float sp = 0.f, sg = 0.f, spp = 0.f, sgg = 0.f, spg = 0.f;

    // 4 batches of 8 rows: 16 outstanding loads per batch per lane,
    // ~64 outstanding per warp-scheduler slot -> hides DRAM latency.
    #pragma unroll
    for (int i0 = 0; i0 < BOX_P; i0 += 8) {
        float p[8], g[8];
        #pragma unroll
        for (int r = 0; r < 8; r++) {
            const size_t off = (size_t)(i0 + r) * W;
            p[r] = __ldg(pbase + off);
            g[r] = __ldg(gbase + off);
        }
        #pragma unroll
        for (int r = 0; r < 8; r++) {
            sp  += p[r];
            sg  += g[r];
            spp += p[r] * p[r];
            sgg += g[r] * g[r];
            spg += p[r] * g[r];
        }
    }

    // Warp-only reduction (no smem, no __syncthreads)
    #pragma unroll
    for (int off = 16; off > 0; off >>= 1) {
        sp  += __shfl_down_sync(0xFFFFFFFFu, sp,  off);
        sg  += __shfl_down_sync(0xFFFFFFFFu, sg,  off);
        spp += __shfl_down_sync(0xFFFFFFFFu, spp, off);
        sgg += __shfl_down_sync(0xFFFFFFFFu, sgg, off);
        spg += __shfl_down_sync(0xFFFFFFFFu, spg, off);
    }

    if (lane == 0) {
        const float P    = (float)PATCH_ELEMS;
        const float invP = 1.0f / P;
        const float mp = sp * invP;
        const float mg = sg * invP;
        // unbiased (ddof=1) variance, matching jnp.std(ddof=1)
        const float varp = (spp - sp * mp) / (P - 1.0f);
        const float varg = (sgg - sg * mg) / (P - 1.0f);
        const float sdp = sqrtf(fmaxf(varp, 0.f)) + EPSF;
        const float sdg = sqrtf(fmaxf(varg, 0.f)) + EPSF;
        const float cov = spg - sp * mg;   // = Spg - Sp*Sg/P
        const float co  = cov / (P * sdp * sdg);
        atomicAdd(out, (1.0f - co) / (float)n_corr);
    }
}

extern "C" void kernel_launch(void* const* d_in, const int* in_sizes, int n_in,
                              void* d_out, int out_size)
{
    const float* pred = (const float*)d_in[0];
    const float* gt   = (const float*)d_in[1];
    const int*   x0   = (const int*)d_in[2];
    const int*   y0   = (const int*)d_in[3];
    float* out = (float*)d_out;

    const int n_corr = in_sizes[2];

    // Derive W from the (square, C=1) image element count.
    int W = 1;
    while ((long long)W * W < (long long)in_sizes[0]) W <<= 1;

    const int grid = (n_corr + WARPS_PER_CTA - 1) / WARPS_PER_CTA;
    lp_zero_out<<<1, 32>>>(out);
    lp_pearson_warp_kernel<<<grid, THREADS>>>(pred, gt, x0, y0, out, n_corr, W);
}

// round 4
// speedup vs baseline: 1.1622x; 1.0744x over previous
#include <cuda_runtime.h>
#include <cuda_bf16.h>
#include <math.h>

#define BOX_P 32
#define PATCH_ELEMS (BOX_P * BOX_P)   // 1024
#define ROWS_PER_WARP 16              // 2 warps per patch
#define WARPS_PER_CTA 8               // -> 4 patches per CTA
#define PATCHES_PER_CTA (WARPS_PER_CTA / 2)
#define THREADS (WARPS_PER_CTA * 32)
#define EPSF 1e-6f

__global__ void lp_zero_out(float* out) {
    if (threadIdx.x == 0) out[0] = 0.0f;
}

__global__ __launch_bounds__(THREADS)
void lp_pearson_2warp_kernel(const float* __restrict__ pred,
                             const float* __restrict__ gt,
                             const int*   __restrict__ x0,
                             const int*   __restrict__ y0,
                             float* __restrict__ out,
                             int n_corr, int W)
{
    const int warp = threadIdx.x >> 5;
    const int lane = threadIdx.x & 31;
    const int patch_local = warp >> 1;          // 0..3
    const int half = warp & 1;                  // 0: rows 0-15, 1: rows 16-31
    const int b = blockIdx.x * PATCHES_PER_CTA + patch_local;

    __shared__ float sh[WARPS_PER_CTA][5];

    float sp = 0.f, sg = 0.f, spp = 0.f, sgg = 0.f, spg = 0.f;

    if (b < n_corr) {
        const int X = x0[b] + half * ROWS_PER_WARP;
        const int Y = y0[b];
        const float* __restrict__ pbase = pred + (size_t)X * W + Y + lane;
        const float* __restrict__ gbase = gt   + (size_t)X * W + Y + lane;

        // Single front-batch of 32 loads per lane -> max outstanding requests,
        // deepest DRAM queues chip-wide.
        float p[ROWS_PER_WARP], g[ROWS_PER_WARP];
        #pragma unroll
        for (int r = 0; r < ROWS_PER_WARP; r++) {
            const size_t off = (size_t)r * W;
            p[r] = __ldg(pbase + off);
            g[r] = __ldg(gbase + off);
        }
        #pragma unroll
        for (int r = 0; r < ROWS_PER_WARP; r++) {
            sp  += p[r];
            sg  += g[r];
            spp += p[r] * p[r];
            sgg += g[r] * g[r];
            spg += p[r] * g[r];
        }
    }

    // Warp reduction of the 5 partial sums
    #pragma unroll
    for (int off = 16; off > 0; off >>= 1) {
        sp  += __shfl_down_sync(0xFFFFFFFFu, sp,  off);
        sg  += __shfl_down_sync(0xFFFFFFFFu, sg,  off);
        spp += __shfl_down_sync(0xFFFFFFFFu, spp, off);
        sgg += __shfl_down_sync(0xFFFFFFFFu, sgg, off);
        spg += __shfl_down_sync(0xFFFFFFFFu, spg, off);
    }

    if (lane == 0) {
        sh[warp][0] = sp;  sh[warp][1] = sg;  sh[warp][2] = spp;
        sh[warp][3] = sgg; sh[warp][4] = spg;
    }
    __syncthreads();

    // Even warp's lane 0 combines the pair and finalizes its patch.
    if (half == 0 && lane == 0 && b < n_corr) {
        const int w2 = warp + 1;
        const float Sp  = sh[warp][0] + sh[w2][0];
        const float Sg  = sh[warp][1] + sh[w2][1];
        const float Spp = sh[warp][2] + sh[w2][2];
        const float Sgg = sh[warp][3] + sh[w2][3];
        const float Spg = sh[warp][4] + sh[w2][4];

        const float P    = (float)PATCH_ELEMS;
        const float invP = 1.0f / P;
        const float mp = Sp * invP;
        const float mg = Sg * invP;
        // unbiased (ddof=1) variance, matching jnp.std(ddof=1)
        const float varp = (Spp - Sp * mp) / (P - 1.0f);
        const float varg = (Sgg - Sg * mg) / (P - 1.0f);
        const float sdp = sqrtf(fmaxf(varp, 0.f)) + EPSF;
        const float sdg = sqrtf(fmaxf(varg, 0.f)) + EPSF;
        const float cov = Spg - Sp * mg;   // = Spg - Sp*Sg/P
        const float co  = cov / (P * sdp * sdg);
        atomicAdd(out, (1.0f - co) / (float)n_corr);
    }
}

extern "C" void kernel_launch(void* const* d_in, const int* in_sizes, int n_in,
                              void* d_out, int out_size)
{
    const float* pred = (const float*)d_in[0];
    const float* gt   = (const float*)d_in[1];
    const int*   x0   = (const int*)d_in[2];
    const int*   y0   = (const int*)d_in[3];
    float* out = (float*)d_out;

    const int n_corr = in_sizes[2];

    // Derive W from the (square, C=1) image element count.
    int W = 1;
    while ((long long)W * W < (long long)in_sizes[0]) W <<= 1;

    const int grid = (n_corr + PATCHES_PER_CTA - 1) / PATCHES_PER_CTA;
    lp_zero_out<<<1, 32>>>(out);
    lp_pearson_2warp_kernel<<<grid, THREADS>>>(pred, gt, x0, y0, out, n_corr, W);
}

// round 5
// speedup vs baseline: 1.1727x; 1.0090x over previous
#include <cuda_runtime.h>
#include <cuda_bf16.h>
#include <math.h>

#define BOX_P 32
#define PATCH_ELEMS (BOX_P * BOX_P)   // 1024
#define WARPS_PER_PATCH 4
#define ROWS_PER_WARP (BOX_P / WARPS_PER_PATCH)   // 8
#define WARPS_PER_CTA 8
#define PATCHES_PER_CTA (WARPS_PER_CTA / WARPS_PER_PATCH)  // 2
#define THREADS (WARPS_PER_CTA * 32)
#define EPSF 1e-6f

__global__ void lp_zero_out(float* out) {
    if (threadIdx.x == 0) out[0] = 0.0f;
}

__global__ __launch_bounds__(THREADS)
void lp_pearson_4warp_kernel(const float* __restrict__ pred,
                             const float* __restrict__ gt,
                             const int*   __restrict__ x0,
                             const int*   __restrict__ y0,
                             float* __restrict__ out,
                             int n_corr, int W)
{
    const int warp    = threadIdx.x >> 5;
    const int lane    = threadIdx.x & 31;
    const int plocal  = warp >> 2;          // 0..1: which patch in CTA
    const int quarter = warp & 3;           // 0..3: which 8-row slab
    const int b = blockIdx.x * PATCHES_PER_CTA + plocal;

    __shared__ float sh[WARPS_PER_CTA][5];

    float sp = 0.f, sg = 0.f, spp = 0.f, sgg = 0.f, spg = 0.f;

    if (b < n_corr) {
        const int X = x0[b] + quarter * ROWS_PER_WARP;
        const int Y = y0[b];
        const float* __restrict__ pbase = pred + (size_t)X * W + Y + lane;
        const float* __restrict__ gbase = gt   + (size_t)X * W + Y + lane;

        // Single front-batch of 16 loads per lane.
        float p[ROWS_PER_WARP], g[ROWS_PER_WARP];
        #pragma unroll
        for (int r = 0; r < ROWS_PER_WARP; r++) {
            const size_t off = (size_t)r * W;
            p[r] = __ldg(pbase + off);
            g[r] = __ldg(gbase + off);
        }
        #pragma unroll
        for (int r = 0; r < ROWS_PER_WARP; r++) {
            sp  += p[r];
            sg  += g[r];
            spp += p[r] * p[r];
            sgg += g[r] * g[r];
            spg += p[r] * g[r];
        }
    }

    // Warp reduction of the 5 partial sums
    #pragma unroll
    for (int off = 16; off > 0; off >>= 1) {
        sp  += __shfl_down_sync(0xFFFFFFFFu, sp,  off);
        sg  += __shfl_down_sync(0xFFFFFFFFu, sg,  off);
        spp += __shfl_down_sync(0xFFFFFFFFu, spp, off);
        sgg += __shfl_down_sync(0xFFFFFFFFu, sgg, off);
        spg += __shfl_down_sync(0xFFFFFFFFu, spg, off);
    }

    if (lane == 0) {
        sh[warp][0] = sp;  sh[warp][1] = sg;  sh[warp][2] = spp;
        sh[warp][3] = sgg; sh[warp][4] = spg;
    }
    __syncthreads();

    // quarter==0 warp's lane 0 combines the 4 slabs and finalizes its patch.
    if (quarter == 0 && lane == 0 && b < n_corr) {
        const int base = plocal * WARPS_PER_PATCH;
        float Sp = 0.f, Sg = 0.f, Spp = 0.f, Sgg = 0.f, Spg = 0.f;
        #pragma unroll
        for (int w = 0; w < WARPS_PER_PATCH; w++) {
            Sp  += sh[base + w][0];
            Sg  += sh[base + w][1];
            Spp += sh[base + w][2];
            Sgg += sh[base + w][3];
            Spg += sh[base + w][4];
        }

        const float P    = (float)PATCH_ELEMS;
        const float invP = 1.0f / P;
        const float mp = Sp * invP;
        const float mg = Sg * invP;
        // unbiased (ddof=1) variance, matching jnp.std(ddof=1)
        const float varp = (Spp - Sp * mp) / (P - 1.0f);
        const float varg = (Sgg - Sg * mg) / (P - 1.0f);
        const float sdp = sqrtf(fmaxf(varp, 0.f)) + EPSF;
        const float sdg = sqrtf(fmaxf(varg, 0.f)) + EPSF;
        const float cov = Spg - Sp * mg;   // = Spg - Sp*Sg/P
        const float co  = cov / (P * sdp * sdg);
        atomicAdd(out, (1.0f - co) / (float)n_corr);
    }
}

extern "C" void kernel_launch(void* const* d_in, const int* in_sizes, int n_in,
                              void* d_out, int out_size)
{
    const float* pred = (const float*)d_in[0];
    const float* gt   = (const float*)d_in[1];
    const int*   x0   = (const int*)d_in[2];
    const int*   y0   = (const int*)d_in[3];
    float* out = (float*)d_out;

    const int n_corr = in_sizes[2];

    // Derive W from the (square, C=1) image element count.
    int W = 1;
    while ((long long)W * W < (long long)in_sizes[0]) W <<= 1;

    const int grid = (n_corr + PATCHES_PER_CTA - 1) / PATCHES_PER_CTA;
    lp_zero_out<<<1, 32>>>(out);
    lp_pearson_4warp_kernel<<<grid, THREADS>>>(pred, gt, x0, y0, out, n_corr, W);
}